// round 1
// baseline (speedup 1.0000x reference)
#include <cuda_runtime.h>

// ---------------------------------------------------------------------------
// Problem constants
//   B=2, N=1024, D=1024, K=8 (circulant), H=16, dh=64
//   circ_linear == dense GEMM with W[p*8+i][q*8+j] = w[p,q,(i-j) mod 8]
// ---------------------------------------------------------------------------
constexpr int DD = 1024;          // model dim
constexpr int MM = 2048;          // B*N rows

// Scratch (no cudaMalloc allowed) -------------------------------------------
__device__ float g_We[4][DD * DD];              // expanded weights, layout B[k][n]
__device__ float g_Q[MM * DD];
__device__ float g_K[MM * DD];
__device__ float g_V[MM * DD];
__device__ float g_O[MM * DD];

// ---------------------------------------------------------------------------
// Expand circulant blocks into dense B matrix:  B[k][n] = w[n/8][k/8][(n-k)&7]
// grid: (DD*DD/256, 4), block 256
// ---------------------------------------------------------------------------
__global__ void expand_kernel(const float* __restrict__ w0,
                              const float* __restrict__ w1,
                              const float* __restrict__ w2,
                              const float* __restrict__ w3)
{
    const float* w;
    switch (blockIdx.y) {
        case 0:  w = w0; break;
        case 1:  w = w1; break;
        case 2:  w = w2; break;
        default: w = w3; break;
    }
    float* dst = g_We[blockIdx.y];
    int idx = blockIdx.x * 256 + threadIdx.x;     // 0 .. DD*DD-1
    int k = idx >> 10;
    int n = idx & 1023;
    dst[idx] = w[((n >> 3) << 10) + ((k >> 3) << 3) + ((n - k) & 7)];
}

// ---------------------------------------------------------------------------
// Tiled SGEMM with bias:  C[M=2048, N=1024] = A[2048,1024] * B[1024,1024] + b
// BM=BN=128, BK=8, TM=TN=8, 256 threads. blockIdx.z selects (B, bias, C).
// ---------------------------------------------------------------------------
__global__ __launch_bounds__(256)
void sgemm_bias(const float* __restrict__ A,
                const float* __restrict__ B0, const float* __restrict__ B1,
                const float* __restrict__ B2,
                const float* __restrict__ bi0, const float* __restrict__ bi1,
                const float* __restrict__ bi2,
                float* __restrict__ C0, float* __restrict__ C1,
                float* __restrict__ C2)
{
    const float* Bm; const float* bias; float* C;
    if (blockIdx.z == 0)      { Bm = B0; bias = bi0; C = C0; }
    else if (blockIdx.z == 1) { Bm = B1; bias = bi1; C = C1; }
    else                      { Bm = B2; bias = bi2; C = C2; }

    __shared__ float As[8][128];   // transposed A tile
    __shared__ float Bs[8][128];

    const int tid  = threadIdx.x;
    const int cRow = blockIdx.y * 128;
    const int cCol = blockIdx.x * 128;

    const float* Ab = A  + (size_t)cRow * DD;
    const float* Bb = Bm + cCol;
    float*       Cb = C  + (size_t)cRow * DD + cCol;

    const int aRow = tid >> 1;
    const int aCol = (tid & 1) * 4;
    const int bRow = tid >> 5;
    const int bCol = (tid & 31) * 4;
    const int tr   = (tid >> 4) * 8;
    const int tc   = (tid & 15) * 8;

    float acc[8][8];
#pragma unroll
    for (int i = 0; i < 8; i++)
#pragma unroll
        for (int j = 0; j < 8; j++) acc[i][j] = 0.f;

    for (int k0 = 0; k0 < DD; k0 += 8) {
        float4 a4 = *(const float4*)(Ab + (size_t)aRow * DD + k0 + aCol);
        As[aCol + 0][aRow] = a4.x;
        As[aCol + 1][aRow] = a4.y;
        As[aCol + 2][aRow] = a4.z;
        As[aCol + 3][aRow] = a4.w;
        *(float4*)&Bs[bRow][bCol] =
            *(const float4*)(Bb + (size_t)(k0 + bRow) * DD + bCol);
        __syncthreads();

#pragma unroll
        for (int k = 0; k < 8; k++) {
            float4 m0 = *(const float4*)&As[k][tr];
            float4 m1 = *(const float4*)&As[k][tr + 4];
            float4 n0 = *(const float4*)&Bs[k][tc];
            float4 n1 = *(const float4*)&Bs[k][tc + 4];
            float rM[8] = {m0.x, m0.y, m0.z, m0.w, m1.x, m1.y, m1.z, m1.w};
            float rN[8] = {n0.x, n0.y, n0.z, n0.w, n1.x, n1.y, n1.z, n1.w};
#pragma unroll
            for (int i = 0; i < 8; i++)
#pragma unroll
                for (int j = 0; j < 8; j++)
                    acc[i][j] += rM[i] * rN[j];
        }
        __syncthreads();
    }

#pragma unroll
    for (int i = 0; i < 8; i++) {
#pragma unroll
        for (int j = 0; j < 8; j += 4) {
            float4 o;
            o.x = acc[i][j + 0] + bias[cCol + tc + j + 0];
            o.y = acc[i][j + 1] + bias[cCol + tc + j + 1];
            o.z = acc[i][j + 2] + bias[cCol + tc + j + 2];
            o.w = acc[i][j + 3] + bias[cCol + tc + j + 3];
            *(float4*)(Cb + (size_t)(tr + i) * DD + tc + j) = o;
        }
    }
}

// ---------------------------------------------------------------------------
// Causal flash attention. One thread = one query row. 128 rows / CTA.
// KV processed in tiles of 32 rows. dh = 64, scale = 1/sqrt(64) = 0.125.
// grid: (8, B*H=32), block 128.
// Layout of Q/K/V/O: [B, N, D] with head h at columns h*64 .. h*64+63.
// ---------------------------------------------------------------------------
__global__ __launch_bounds__(128)
void flash_kernel(const float* __restrict__ Q, const float* __restrict__ Km,
                  const float* __restrict__ V, float* __restrict__ O)
{
    __shared__ float Kt[64][36];   // K tile transposed: Kt[k][c], row padded to 36 (16B aligned)
    __shared__ float Vs[32][64];   // V tile natural
    __shared__ float Ps[32][128];  // per-thread probabilities (column = thread)

    const int tid = threadIdx.x;
    const int bh  = blockIdx.y;
    const int h   = bh & 15;
    const int b   = bh >> 4;
    const int i0  = (7 - blockIdx.x) * 128;   // heavy CTAs first
    const int r   = i0 + tid;                 // this thread's query row

    const size_t base = ((size_t)b * 1024) * DD + (size_t)h * 64;
    const float* qrow = Q + base + (size_t)r * DD;

    float o[64];
#pragma unroll
    for (int d = 0; d < 64; d++) o[d] = 0.f;
    float m = -1e30f, l = 0.f;

    const int nb = (i0 >> 5) + 4;             // kv tiles up to row i0+127
    for (int jb = 0; jb < nb; jb++) {
        const int j0 = jb * 32;
        __syncthreads();
        // cooperative load: 32x64 K (transposed) and V tiles, 512 float4 each
        for (int f = tid; f < 512; f += 128) {
            int row = f >> 4;
            int c4  = (f & 15) * 4;
            float4 k4 = *(const float4*)(Km + base + (size_t)(j0 + row) * DD + c4);
            Kt[c4 + 0][row] = k4.x;
            Kt[c4 + 1][row] = k4.y;
            Kt[c4 + 2][row] = k4.z;
            Kt[c4 + 3][row] = k4.w;
            *(float4*)&Vs[row][c4] =
                *(const float4*)(V + base + (size_t)(j0 + row) * DD + c4);
        }
        __syncthreads();

        // S = q . K^T  (32 scores per thread)
        float s[32];
#pragma unroll
        for (int c = 0; c < 32; c++) s[c] = 0.f;
        for (int k = 0; k < 64; k++) {
            float qk = __ldg(qrow + k);        // L1-resident after first tile
#pragma unroll
            for (int c4 = 0; c4 < 8; c4++) {
                float4 kv = *(const float4*)&Kt[k][c4 * 4];
                s[c4 * 4 + 0] += qk * kv.x;
                s[c4 * 4 + 1] += qk * kv.y;
                s[c4 * 4 + 2] += qk * kv.z;
                s[c4 * 4 + 3] += qk * kv.w;
            }
        }

        // causal mask + online softmax
        const bool full = (j0 + 31) <= r;
        float mb = -1e30f;
#pragma unroll
        for (int c = 0; c < 32; c++) {
            float sc = s[c] * 0.125f;
            if (!full && (j0 + c) > r) sc = -1e30f;
            s[c] = sc;
            mb = fmaxf(mb, sc);
        }
        float mn = fmaxf(m, mb);
        float alpha = __expf(m - mn);
        float ps = 0.f;
#pragma unroll
        for (int c = 0; c < 32; c++) {
            float p = __expf(s[c] - mn);
            ps += p;
            Ps[c][tid] = p;                    // stash so O-loop can stay rolled
        }
        l = l * alpha + ps;
        m = mn;
#pragma unroll
        for (int d = 0; d < 64; d++) o[d] *= alpha;

        for (int c = 0; c < 32; c++) {         // rolled: small I-footprint
            float p = Ps[c][tid];
#pragma unroll
            for (int d4 = 0; d4 < 16; d4++) {
                float4 vv = *(const float4*)&Vs[c][d4 * 4];
                o[d4 * 4 + 0] += p * vv.x;
                o[d4 * 4 + 1] += p * vv.y;
                o[d4 * 4 + 2] += p * vv.z;
                o[d4 * 4 + 3] += p * vv.w;
            }
        }
    }

    const float inv = 1.f / l;
    float* op = O + base + (size_t)r * DD;
#pragma unroll
    for (int d4 = 0; d4 < 16; d4++) {
        float4 vv;
        vv.x = o[d4 * 4 + 0] * inv;
        vv.y = o[d4 * 4 + 1] * inv;
        vv.z = o[d4 * 4 + 2] * inv;
        vv.w = o[d4 * 4 + 3] * inv;
        *(float4*)(op + d4 * 4) = vv;
    }
}

// ---------------------------------------------------------------------------
// Inputs (metadata order): x, mask(unused), wq, bq, wk, bk, wv, bv, wo, bo
// ---------------------------------------------------------------------------
extern "C" void kernel_launch(void* const* d_in, const int* in_sizes, int n_in,
                              void* d_out, int out_size)
{
    (void)in_sizes; (void)n_in; (void)out_size;
    const float* x  = (const float*)d_in[0];
    const float* wq = (const float*)d_in[2];
    const float* bq = (const float*)d_in[3];
    const float* wk = (const float*)d_in[4];
    const float* bk = (const float*)d_in[5];
    const float* wv = (const float*)d_in[6];
    const float* bv = (const float*)d_in[7];
    const float* wo = (const float*)d_in[8];
    const float* bo = (const float*)d_in[9];
    float* out = (float*)d_out;

    float *We, *Qb, *Kb, *Vb, *Ob;
    cudaGetSymbolAddress((void**)&We, g_We);
    cudaGetSymbolAddress((void**)&Qb, g_Q);
    cudaGetSymbolAddress((void**)&Kb, g_K);
    cudaGetSymbolAddress((void**)&Vb, g_V);
    cudaGetSymbolAddress((void**)&Ob, g_O);

    // 1) expand circulant weights to dense B matrices
    expand_kernel<<<dim3(DD * DD / 256, 4), 256>>>(wq, wk, wv, wo);

    // 2) fused Q/K/V projections (one launch, z selects matrix)
    sgemm_bias<<<dim3(DD / 128, MM / 128, 3), 256>>>(
        x, We, We + DD * DD, We + 2 * DD * DD, bq, bk, bv, Qb, Kb, Vb);

    // 3) causal flash attention
    flash_kernel<<<dim3(8, 32), 128>>>(Qb, Kb, Vb, Ob);

    // 4) output projection -> d_out
    sgemm_bias<<<dim3(DD / 128, MM / 128, 1), 256>>>(
        Ob, We + 3 * DD * DD, We + 3 * DD * DD, We + 3 * DD * DD,
        bo, bo, bo, out, out, out);
}

// round 2
// speedup vs baseline: 1.6049x; 1.6049x over previous
#include <cuda_runtime.h>
#include <cstdint>

// ---------------------------------------------------------------------------
// Problem constants: B=2, N=1024, D=1024, K=8 (circulant), H=16, dh=64
// circ_linear == dense GEMM with W[p*8+i][q*8+j] = w[p,q,(i-j) mod 8]
// ---------------------------------------------------------------------------
constexpr int DD = 1024;
constexpr int MM = 2048;

__device__ float g_We[4][DD * DD];   // expanded weights, layout B[k][n]
__device__ float g_Q[MM * DD];
__device__ float g_K[MM * DD];
__device__ float g_V[MM * DD];
__device__ float g_O[MM * DD];

// ---------------------------------------------------------------------------
// Expand circulant blocks: dst[k][n] = w[n/8][k/8][(n-k)&7]
// ---------------------------------------------------------------------------
__global__ void expand_kernel(const float* __restrict__ w0,
                              const float* __restrict__ w1,
                              const float* __restrict__ w2,
                              const float* __restrict__ w3)
{
    const float* w;
    switch (blockIdx.y) {
        case 0:  w = w0; break;
        case 1:  w = w1; break;
        case 2:  w = w2; break;
        default: w = w3; break;
    }
    float* dst = g_We[blockIdx.y];
    int idx = blockIdx.x * 256 + threadIdx.x;
    int k = idx >> 10;
    int n = idx & 1023;
    dst[idx] = w[((n >> 3) << 10) + ((k >> 3) << 3) + ((n - k) & 7)];
}

// ---------------------------------------------------------------------------
// TF32 tensor-core GEMM:  C[2048,1024] = A * B + bias
// CTA tile 128x128, 8 warps of 32x64, BK=16, double-buffered smem.
// mma.sync.aligned.m16n8k8.row.col.f32.tf32.tf32.f32
// ---------------------------------------------------------------------------
__device__ __forceinline__ uint32_t f2tf32(float f) {
    uint32_t r;
    asm("cvt.rna.tf32.f32 %0, %1;" : "=r"(r) : "f"(f));
    return r;
}

constexpr int AST = 20;    // A smem row stride (floats):  [m][k], 16 + 4 pad
constexpr int BST = 136;   // B smem row stride (floats):  [k][n], 128 + 8 pad

__global__ __launch_bounds__(256, 2)
void gemm_tf32(const float* __restrict__ A,
               const float* __restrict__ B0, const float* __restrict__ B1,
               const float* __restrict__ B2,
               const float* __restrict__ bi0, const float* __restrict__ bi1,
               const float* __restrict__ bi2,
               float* __restrict__ C0, float* __restrict__ C1,
               float* __restrict__ C2)
{
    const float* Bm; const float* bias; float* C;
    if (blockIdx.z == 0)      { Bm = B0; bias = bi0; C = C0; }
    else if (blockIdx.z == 1) { Bm = B1; bias = bi1; C = C1; }
    else                      { Bm = B2; bias = bi2; C = C2; }

    __shared__ uint32_t As[2][128 * AST];
    __shared__ uint32_t Bs[2][16 * BST];

    const int tid  = threadIdx.x;
    const int warp = tid >> 5;
    const int lane = tid & 31;
    const int grp  = lane >> 2;   // 0..7
    const int q    = lane & 3;    // 0..3

    const int cRow = blockIdx.y * 128;
    const int cCol = blockIdx.x * 128;
    const int wm   = (warp & 3) * 32;
    const int wn   = (warp >> 2) * 64;

    // global load mapping (coalesced float4)
    const int am = tid >> 2;            // 0..63 (+64 for second load)
    const int ak = (tid & 3) * 4;
    const int bkRow = tid >> 5;         // 0..7 (+8 for second load)
    const int bn = (lane) * 4;

    const float* Ap = A  + (size_t)(cRow + am) * DD + ak;
    const float* Bp = Bm + (size_t)bkRow * DD + cCol + bn;

    float acc[2][8][4];
#pragma unroll
    for (int mi = 0; mi < 2; mi++)
#pragma unroll
        for (int ni = 0; ni < 8; ni++)
#pragma unroll
            for (int c = 0; c < 4; c++) acc[mi][ni][c] = 0.f;

    // ---- load first tile ----
    {
        float4 a0 = *(const float4*)(Ap);
        float4 a1 = *(const float4*)(Ap + 64 * DD);
        float4 b0 = *(const float4*)(Bp);
        float4 b1 = *(const float4*)(Bp + 8 * DD);
        *(uint4*)&As[0][am * AST + ak] =
            make_uint4(f2tf32(a0.x), f2tf32(a0.y), f2tf32(a0.z), f2tf32(a0.w));
        *(uint4*)&As[0][(am + 64) * AST + ak] =
            make_uint4(f2tf32(a1.x), f2tf32(a1.y), f2tf32(a1.z), f2tf32(a1.w));
        *(uint4*)&Bs[0][bkRow * BST + bn] =
            make_uint4(f2tf32(b0.x), f2tf32(b0.y), f2tf32(b0.z), f2tf32(b0.w));
        *(uint4*)&Bs[0][(bkRow + 8) * BST + bn] =
            make_uint4(f2tf32(b1.x), f2tf32(b1.y), f2tf32(b1.z), f2tf32(b1.w));
    }
    __syncthreads();

    int buf = 0;
    for (int k0 = 0; k0 < DD; k0 += 16) {
        const bool has_next = (k0 + 16 < DD);
        float4 pa0, pa1, pb0, pb1;
        if (has_next) {
            const int kn = k0 + 16;
            pa0 = *(const float4*)(Ap + kn);
            pa1 = *(const float4*)(Ap + 64 * DD + kn);
            pb0 = *(const float4*)(Bp + (size_t)kn * DD);
            pb1 = *(const float4*)(Bp + (size_t)(kn + 8) * DD);
        }

        const uint32_t* as = As[buf];
        const uint32_t* bs = Bs[buf];
#pragma unroll
        for (int kk = 0; kk < 16; kk += 8) {
            uint32_t af[2][4];
#pragma unroll
            for (int mi = 0; mi < 2; mi++) {
                int m = wm + mi * 16 + grp;
                af[mi][0] = as[m * AST + kk + q];
                af[mi][1] = as[(m + 8) * AST + kk + q];
                af[mi][2] = as[m * AST + kk + q + 4];
                af[mi][3] = as[(m + 8) * AST + kk + q + 4];
            }
            uint32_t bf[8][2];
#pragma unroll
            for (int ni = 0; ni < 8; ni++) {
                bf[ni][0] = bs[(kk + q) * BST + wn + ni * 8 + grp];
                bf[ni][1] = bs[(kk + q + 4) * BST + wn + ni * 8 + grp];
            }
#pragma unroll
            for (int mi = 0; mi < 2; mi++)
#pragma unroll
                for (int ni = 0; ni < 8; ni++) {
                    asm volatile(
                        "mma.sync.aligned.m16n8k8.row.col.f32.tf32.tf32.f32 "
                        "{%0,%1,%2,%3}, {%4,%5,%6,%7}, {%8,%9}, {%0,%1,%2,%3};"
                        : "+f"(acc[mi][ni][0]), "+f"(acc[mi][ni][1]),
                          "+f"(acc[mi][ni][2]), "+f"(acc[mi][ni][3])
                        : "r"(af[mi][0]), "r"(af[mi][1]),
                          "r"(af[mi][2]), "r"(af[mi][3]),
                          "r"(bf[ni][0]), "r"(bf[ni][1]));
                }
        }

        if (has_next) {
            uint32_t* asn = As[buf ^ 1];
            uint32_t* bsn = Bs[buf ^ 1];
            *(uint4*)&asn[am * AST + ak] =
                make_uint4(f2tf32(pa0.x), f2tf32(pa0.y), f2tf32(pa0.z), f2tf32(pa0.w));
            *(uint4*)&asn[(am + 64) * AST + ak] =
                make_uint4(f2tf32(pa1.x), f2tf32(pa1.y), f2tf32(pa1.z), f2tf32(pa1.w));
            *(uint4*)&bsn[bkRow * BST + bn] =
                make_uint4(f2tf32(pb0.x), f2tf32(pb0.y), f2tf32(pb0.z), f2tf32(pb0.w));
            *(uint4*)&bsn[(bkRow + 8) * BST + bn] =
                make_uint4(f2tf32(pb1.x), f2tf32(pb1.y), f2tf32(pb1.z), f2tf32(pb1.w));
            __syncthreads();
            buf ^= 1;
        }
    }

    // ---- epilogue: add bias, store ----
#pragma unroll
    for (int mi = 0; mi < 2; mi++) {
#pragma unroll
        for (int ni = 0; ni < 8; ni++) {
            int row = cRow + wm + mi * 16 + grp;
            int col = cCol + wn + ni * 8 + q * 2;
            float bx = bias[col], by = bias[col + 1];
            float2 v0 = make_float2(acc[mi][ni][0] + bx, acc[mi][ni][1] + by);
            float2 v1 = make_float2(acc[mi][ni][2] + bx, acc[mi][ni][3] + by);
            *(float2*)(C + (size_t)row * DD + col)       = v0;
            *(float2*)(C + (size_t)(row + 8) * DD + col) = v1;
        }
    }
}

// ---------------------------------------------------------------------------
// Causal flash attention (unchanged from R1; fp32 scalar)
// ---------------------------------------------------------------------------
__global__ __launch_bounds__(128)
void flash_kernel(const float* __restrict__ Q, const float* __restrict__ Km,
                  const float* __restrict__ V, float* __restrict__ O)
{
    __shared__ float Kt[64][36];
    __shared__ float Vs[32][64];
    __shared__ float Ps[32][128];

    const int tid = threadIdx.x;
    const int bh  = blockIdx.y;
    const int h   = bh & 15;
    const int b   = bh >> 4;
    const int i0  = (7 - blockIdx.x) * 128;
    const int r   = i0 + tid;

    const size_t base = ((size_t)b * 1024) * DD + (size_t)h * 64;
    const float* qrow = Q + base + (size_t)r * DD;

    float o[64];
#pragma unroll
    for (int d = 0; d < 64; d++) o[d] = 0.f;
    float m = -1e30f, l = 0.f;

    const int nb = (i0 >> 5) + 4;
    for (int jb = 0; jb < nb; jb++) {
        const int j0 = jb * 32;
        __syncthreads();
        for (int f = tid; f < 512; f += 128) {
            int row = f >> 4;
            int c4  = (f & 15) * 4;
            float4 k4 = *(const float4*)(Km + base + (size_t)(j0 + row) * DD + c4);
            Kt[c4 + 0][row] = k4.x;
            Kt[c4 + 1][row] = k4.y;
            Kt[c4 + 2][row] = k4.z;
            Kt[c4 + 3][row] = k4.w;
            *(float4*)&Vs[row][c4] =
                *(const float4*)(V + base + (size_t)(j0 + row) * DD + c4);
        }
        __syncthreads();

        float s[32];
#pragma unroll
        for (int c = 0; c < 32; c++) s[c] = 0.f;
        for (int k = 0; k < 64; k++) {
            float qk = __ldg(qrow + k);
#pragma unroll
            for (int c4 = 0; c4 < 8; c4++) {
                float4 kv = *(const float4*)&Kt[k][c4 * 4];
                s[c4 * 4 + 0] += qk * kv.x;
                s[c4 * 4 + 1] += qk * kv.y;
                s[c4 * 4 + 2] += qk * kv.z;
                s[c4 * 4 + 3] += qk * kv.w;
            }
        }

        const bool full = (j0 + 31) <= r;
        float mb = -1e30f;
#pragma unroll
        for (int c = 0; c < 32; c++) {
            float sc = s[c] * 0.125f;
            if (!full && (j0 + c) > r) sc = -1e30f;
            s[c] = sc;
            mb = fmaxf(mb, sc);
        }
        float mn = fmaxf(m, mb);
        float alpha = __expf(m - mn);
        float ps = 0.f;
#pragma unroll
        for (int c = 0; c < 32; c++) {
            float p = __expf(s[c] - mn);
            ps += p;
            Ps[c][tid] = p;
        }
        l = l * alpha + ps;
        m = mn;
#pragma unroll
        for (int d = 0; d < 64; d++) o[d] *= alpha;

        for (int c = 0; c < 32; c++) {
            float p = Ps[c][tid];
#pragma unroll
            for (int d4 = 0; d4 < 16; d4++) {
                float4 vv = *(const float4*)&Vs[c][d4 * 4];
                o[d4 * 4 + 0] += p * vv.x;
                o[d4 * 4 + 1] += p * vv.y;
                o[d4 * 4 + 2] += p * vv.z;
                o[d4 * 4 + 3] += p * vv.w;
            }
        }
    }

    const float inv = 1.f / l;
    float* op = O + base + (size_t)r * DD;
#pragma unroll
    for (int d4 = 0; d4 < 16; d4++) {
        float4 vv;
        vv.x = o[d4 * 4 + 0] * inv;
        vv.y = o[d4 * 4 + 1] * inv;
        vv.z = o[d4 * 4 + 2] * inv;
        vv.w = o[d4 * 4 + 3] * inv;
        *(float4*)(op + d4 * 4) = vv;
    }
}

// ---------------------------------------------------------------------------
extern "C" void kernel_launch(void* const* d_in, const int* in_sizes, int n_in,
                              void* d_out, int out_size)
{
    (void)in_sizes; (void)n_in; (void)out_size;
    const float* x  = (const float*)d_in[0];
    const float* wq = (const float*)d_in[2];
    const float* bq = (const float*)d_in[3];
    const float* wk = (const float*)d_in[4];
    const float* bk = (const float*)d_in[5];
    const float* wv = (const float*)d_in[6];
    const float* bv = (const float*)d_in[7];
    const float* wo = (const float*)d_in[8];
    const float* bo = (const float*)d_in[9];
    float* out = (float*)d_out;

    float *We, *Qb, *Kb, *Vb, *Ob;
    cudaGetSymbolAddress((void**)&We, g_We);
    cudaGetSymbolAddress((void**)&Qb, g_Q);
    cudaGetSymbolAddress((void**)&Kb, g_K);
    cudaGetSymbolAddress((void**)&Vb, g_V);
    cudaGetSymbolAddress((void**)&Ob, g_O);

    expand_kernel<<<dim3(DD * DD / 256, 4), 256>>>(wq, wk, wv, wo);

    gemm_tf32<<<dim3(DD / 128, MM / 128, 3), 256>>>(
        x, We, We + DD * DD, We + 2 * DD * DD, bq, bk, bv, Qb, Kb, Vb);

    flash_kernel<<<dim3(8, 32), 128>>>(Qb, Kb, Vb, Ob);

    gemm_tf32<<<dim3(DD / 128, MM / 128, 1), 256>>>(
        Ob, We + 3 * DD * DD, We + 3 * DD * DD, We + 3 * DD * DD,
        bo, bo, bo, out, out, out);
}

// round 3
// speedup vs baseline: 5.6251x; 3.5050x over previous
#include <cuda_runtime.h>
#include <cstdint>

// ---------------------------------------------------------------------------
// B=2, N=1024, D=1024, K=8 (circulant), H=16, dh=64
// circ_linear == dense GEMM with W[p*8+i][q*8+j] = w[p,q,(i-j) mod 8]
// ---------------------------------------------------------------------------
constexpr int DD = 1024;
constexpr int MM = 2048;

__device__ float g_We[4][DD * DD];   // expanded weights, layout B[k][n]
__device__ float g_Q[MM * DD];
__device__ float g_K[MM * DD];
__device__ float g_V[MM * DD];
__device__ float g_O[MM * DD];

__device__ __forceinline__ uint32_t f2tf32(float f) {
    uint32_t r;
    asm("cvt.rna.tf32.f32 %0, %1;" : "=r"(r) : "f"(f));
    return r;
}

#define MMA_TF32(ACC, AF, BF)                                            \
    asm volatile(                                                        \
        "mma.sync.aligned.m16n8k8.row.col.f32.tf32.tf32.f32 "            \
        "{%0,%1,%2,%3}, {%4,%5,%6,%7}, {%8,%9}, {%0,%1,%2,%3};"          \
        : "+f"((ACC)[0]), "+f"((ACC)[1]), "+f"((ACC)[2]), "+f"((ACC)[3]) \
        : "r"((AF)[0]), "r"((AF)[1]), "r"((AF)[2]), "r"((AF)[3]),        \
          "r"((BF)[0]), "r"((BF)[1]))

// ---------------------------------------------------------------------------
// Expand circulant blocks: dst[k][n] = w[n/8][k/8][(n-k)&7]
// ---------------------------------------------------------------------------
__global__ void expand_kernel(const float* __restrict__ w0,
                              const float* __restrict__ w1,
                              const float* __restrict__ w2,
                              const float* __restrict__ w3)
{
    const float* w;
    switch (blockIdx.y) {
        case 0:  w = w0; break;
        case 1:  w = w1; break;
        case 2:  w = w2; break;
        default: w = w3; break;
    }
    float* dst = g_We[blockIdx.y];
    int idx = blockIdx.x * 256 + threadIdx.x;
    int k = idx >> 10;
    int n = idx & 1023;
    dst[idx] = w[((n >> 3) << 10) + ((k >> 3) << 3) + ((n - k) & 7)];
}

// ---------------------------------------------------------------------------
// TF32 tensor-core GEMM (unchanged from R2): C[2048,1024] = A*B + bias
// ---------------------------------------------------------------------------
constexpr int AST = 20;
constexpr int BST = 136;

__global__ __launch_bounds__(256, 2)
void gemm_tf32(const float* __restrict__ A,
               const float* __restrict__ B0, const float* __restrict__ B1,
               const float* __restrict__ B2,
               const float* __restrict__ bi0, const float* __restrict__ bi1,
               const float* __restrict__ bi2,
               float* __restrict__ C0, float* __restrict__ C1,
               float* __restrict__ C2)
{
    const float* Bm; const float* bias; float* C;
    if (blockIdx.z == 0)      { Bm = B0; bias = bi0; C = C0; }
    else if (blockIdx.z == 1) { Bm = B1; bias = bi1; C = C1; }
    else                      { Bm = B2; bias = bi2; C = C2; }

    __shared__ uint32_t As[2][128 * AST];
    __shared__ uint32_t Bs[2][16 * BST];

    const int tid  = threadIdx.x;
    const int warp = tid >> 5;
    const int lane = tid & 31;
    const int grp  = lane >> 2;
    const int q    = lane & 3;

    const int cRow = blockIdx.y * 128;
    const int cCol = blockIdx.x * 128;
    const int wm   = (warp & 3) * 32;
    const int wn   = (warp >> 2) * 64;

    const int am = tid >> 2;
    const int ak = (tid & 3) * 4;
    const int bkRow = tid >> 5;
    const int bn = lane * 4;

    const float* Ap = A  + (size_t)(cRow + am) * DD + ak;
    const float* Bp = Bm + (size_t)bkRow * DD + cCol + bn;

    float acc[2][8][4];
#pragma unroll
    for (int mi = 0; mi < 2; mi++)
#pragma unroll
        for (int ni = 0; ni < 8; ni++)
#pragma unroll
            for (int c = 0; c < 4; c++) acc[mi][ni][c] = 0.f;

    {
        float4 a0 = *(const float4*)(Ap);
        float4 a1 = *(const float4*)(Ap + 64 * DD);
        float4 b0 = *(const float4*)(Bp);
        float4 b1 = *(const float4*)(Bp + 8 * DD);
        *(uint4*)&As[0][am * AST + ak] =
            make_uint4(f2tf32(a0.x), f2tf32(a0.y), f2tf32(a0.z), f2tf32(a0.w));
        *(uint4*)&As[0][(am + 64) * AST + ak] =
            make_uint4(f2tf32(a1.x), f2tf32(a1.y), f2tf32(a1.z), f2tf32(a1.w));
        *(uint4*)&Bs[0][bkRow * BST + bn] =
            make_uint4(f2tf32(b0.x), f2tf32(b0.y), f2tf32(b0.z), f2tf32(b0.w));
        *(uint4*)&Bs[0][(bkRow + 8) * BST + bn] =
            make_uint4(f2tf32(b1.x), f2tf32(b1.y), f2tf32(b1.z), f2tf32(b1.w));
    }
    __syncthreads();

    int buf = 0;
    for (int k0 = 0; k0 < DD; k0 += 16) {
        const bool has_next = (k0 + 16 < DD);
        float4 pa0, pa1, pb0, pb1;
        if (has_next) {
            const int kn = k0 + 16;
            pa0 = *(const float4*)(Ap + kn);
            pa1 = *(const float4*)(Ap + 64 * DD + kn);
            pb0 = *(const float4*)(Bp + (size_t)kn * DD);
            pb1 = *(const float4*)(Bp + (size_t)(kn + 8) * DD);
        }

        const uint32_t* as = As[buf];
        const uint32_t* bs = Bs[buf];
#pragma unroll
        for (int kk = 0; kk < 16; kk += 8) {
            uint32_t af[2][4];
#pragma unroll
            for (int mi = 0; mi < 2; mi++) {
                int m = wm + mi * 16 + grp;
                af[mi][0] = as[m * AST + kk + q];
                af[mi][1] = as[(m + 8) * AST + kk + q];
                af[mi][2] = as[m * AST + kk + q + 4];
                af[mi][3] = as[(m + 8) * AST + kk + q + 4];
            }
            uint32_t bf[8][2];
#pragma unroll
            for (int ni = 0; ni < 8; ni++) {
                bf[ni][0] = bs[(kk + q) * BST + wn + ni * 8 + grp];
                bf[ni][1] = bs[(kk + q + 4) * BST + wn + ni * 8 + grp];
            }
#pragma unroll
            for (int mi = 0; mi < 2; mi++)
#pragma unroll
                for (int ni = 0; ni < 8; ni++)
                    MMA_TF32(acc[mi][ni], af[mi], bf[ni]);
        }

        if (has_next) {
            uint32_t* asn = As[buf ^ 1];
            uint32_t* bsn = Bs[buf ^ 1];
            *(uint4*)&asn[am * AST + ak] =
                make_uint4(f2tf32(pa0.x), f2tf32(pa0.y), f2tf32(pa0.z), f2tf32(pa0.w));
            *(uint4*)&asn[(am + 64) * AST + ak] =
                make_uint4(f2tf32(pa1.x), f2tf32(pa1.y), f2tf32(pa1.z), f2tf32(pa1.w));
            *(uint4*)&bsn[bkRow * BST + bn] =
                make_uint4(f2tf32(pb0.x), f2tf32(pb0.y), f2tf32(pb0.z), f2tf32(pb0.w));
            *(uint4*)&bsn[(bkRow + 8) * BST + bn] =
                make_uint4(f2tf32(pb1.x), f2tf32(pb1.y), f2tf32(pb1.z), f2tf32(pb1.w));
            __syncthreads();
            buf ^= 1;
        }
    }

#pragma unroll
    for (int mi = 0; mi < 2; mi++) {
#pragma unroll
        for (int ni = 0; ni < 8; ni++) {
            int row = cRow + wm + mi * 16 + grp;
            int col = cCol + wn + ni * 8 + q * 2;
            float bx = bias[col], by = bias[col + 1];
            *(float2*)(C + (size_t)row * DD + col) =
                make_float2(acc[mi][ni][0] + bx, acc[mi][ni][1] + by);
            *(float2*)(C + (size_t)(row + 8) * DD + col) =
                make_float2(acc[mi][ni][2] + bx, acc[mi][ni][3] + by);
        }
    }
}

// ---------------------------------------------------------------------------
// Tensor-core causal flash attention (TF32 mma).
// CTA: 64 q-rows (4 warps x m16), KV tile 64, dh=64.
// grid: (BH=32, 16)  -- y reversed so heavy diagonal CTAs launch first.
// Smem: Ksm (stride 68, doubles as P region), Vsm (stride 72, stages Q first).
// ---------------------------------------------------------------------------
constexpr int KST = 68;
constexpr int VST = 72;

__global__ __launch_bounds__(128, 3)
void flash_mma(const float* __restrict__ Qg, const float* __restrict__ Kg,
               const float* __restrict__ Vg, float* __restrict__ Og)
{
    __shared__ uint32_t Ksm[64 * KST];
    __shared__ uint32_t Vsm[64 * VST];

    const int tid  = threadIdx.x;
    const int warp = tid >> 5;
    const int lane = tid & 31;
    const int grp  = lane >> 2;
    const int q    = lane & 3;

    const int qb = 15 - blockIdx.y;
    const int i0 = qb * 64;
    const int h  = blockIdx.x & 15;
    const int b  = blockIdx.x >> 4;
    const size_t base = (size_t)b * (1024 * 1024) + h * 64;

    const int wm = warp * 16;
    const int r0 = i0 + wm + grp;

    // ---- stage Q tile into Vsm, pull A-fragments into registers ----
#pragma unroll
    for (int it = 0; it < 8; it++) {
        int idx = tid + it * 128;
        int row = idx >> 4;
        int c4  = (idx & 15) << 2;
        *(float4*)&((float*)Vsm)[row * VST + c4] =
            *(const float4*)(Qg + base + (size_t)(i0 + row) * DD + c4);
    }
    __syncthreads();
    uint32_t qf[8][4];
    {
        const float* Qs = (const float*)Vsm;
#pragma unroll
        for (int ks = 0; ks < 8; ks++) {
            qf[ks][0] = f2tf32(Qs[(wm + grp)     * VST + ks * 8 + q]);
            qf[ks][1] = f2tf32(Qs[(wm + grp + 8) * VST + ks * 8 + q]);
            qf[ks][2] = f2tf32(Qs[(wm + grp)     * VST + ks * 8 + q + 4]);
            qf[ks][3] = f2tf32(Qs[(wm + grp + 8) * VST + ks * 8 + q + 4]);
        }
    }
    __syncthreads();

    float oacc[8][4];
#pragma unroll
    for (int nt = 0; nt < 8; nt++)
#pragma unroll
        for (int c = 0; c < 4; c++) oacc[nt][c] = 0.f;
    float m0 = -1e30f, m1 = -1e30f, l0 = 0.f, l1 = 0.f;

    for (int jb = 0; jb <= qb; jb++) {
        const int j0 = jb * 64;

        // ---- load K,V tiles (tf32-converted at store) ----
#pragma unroll
        for (int it = 0; it < 8; it++) {
            int idx = tid + it * 128;
            int row = idx >> 4;
            int c4  = (idx & 15) << 2;
            float4 k4 = *(const float4*)(Kg + base + (size_t)(j0 + row) * DD + c4);
            float4 v4 = *(const float4*)(Vg + base + (size_t)(j0 + row) * DD + c4);
            *(uint4*)&Ksm[row * KST + c4] =
                make_uint4(f2tf32(k4.x), f2tf32(k4.y), f2tf32(k4.z), f2tf32(k4.w));
            *(uint4*)&Vsm[row * VST + c4] =
                make_uint4(f2tf32(v4.x), f2tf32(v4.y), f2tf32(v4.z), f2tf32(v4.w));
        }
        __syncthreads();

        // ---- S = Q K^T  (m16 x n64 per warp) ----
        float sacc[8][4];
#pragma unroll
        for (int nt = 0; nt < 8; nt++)
#pragma unroll
            for (int c = 0; c < 4; c++) sacc[nt][c] = 0.f;
#pragma unroll
        for (int ks = 0; ks < 8; ks++) {
            uint32_t bf[8][2];
#pragma unroll
            for (int nt = 0; nt < 8; nt++) {
                bf[nt][0] = Ksm[(nt * 8 + grp) * KST + ks * 8 + q];
                bf[nt][1] = Ksm[(nt * 8 + grp) * KST + ks * 8 + q + 4];
            }
#pragma unroll
            for (int nt = 0; nt < 8; nt++)
                MMA_TF32(sacc[nt], qf[ks], bf[nt]);
        }

        // ---- online softmax (C-layout registers) ----
        const bool diag = (jb == qb);
        float mx0 = -1e30f, mx1 = -1e30f;
#pragma unroll
        for (int nt = 0; nt < 8; nt++) {
            float s0 = sacc[nt][0] * 0.125f;
            float s1 = sacc[nt][1] * 0.125f;
            float s2 = sacc[nt][2] * 0.125f;
            float s3 = sacc[nt][3] * 0.125f;
            if (diag) {
                int j = j0 + nt * 8 + q * 2;
                if (j     > r0)     s0 = -1e30f;
                if (j + 1 > r0)     s1 = -1e30f;
                if (j     > r0 + 8) s2 = -1e30f;
                if (j + 1 > r0 + 8) s3 = -1e30f;
            }
            sacc[nt][0] = s0; sacc[nt][1] = s1;
            sacc[nt][2] = s2; sacc[nt][3] = s3;
            mx0 = fmaxf(mx0, fmaxf(s0, s1));
            mx1 = fmaxf(mx1, fmaxf(s2, s3));
        }
        mx0 = fmaxf(mx0, __shfl_xor_sync(0xffffffffu, mx0, 1));
        mx0 = fmaxf(mx0, __shfl_xor_sync(0xffffffffu, mx0, 2));
        mx1 = fmaxf(mx1, __shfl_xor_sync(0xffffffffu, mx1, 1));
        mx1 = fmaxf(mx1, __shfl_xor_sync(0xffffffffu, mx1, 2));
        float mn0 = fmaxf(m0, mx0), mn1 = fmaxf(m1, mx1);
        float al0 = __expf(m0 - mn0), al1 = __expf(m1 - mn1);
        m0 = mn0; m1 = mn1;
        float ps0 = 0.f, ps1 = 0.f;
#pragma unroll
        for (int nt = 0; nt < 8; nt++) {
            float p0 = __expf(sacc[nt][0] - mn0);
            float p1 = __expf(sacc[nt][1] - mn0);
            float p2 = __expf(sacc[nt][2] - mn1);
            float p3 = __expf(sacc[nt][3] - mn1);
            ps0 += p0 + p1;
            ps1 += p2 + p3;
            sacc[nt][0] = p0; sacc[nt][1] = p1;
            sacc[nt][2] = p2; sacc[nt][3] = p3;
        }
        l0 = l0 * al0 + ps0;
        l1 = l1 * al1 + ps1;
#pragma unroll
        for (int nt = 0; nt < 8; nt++) {
            oacc[nt][0] *= al0; oacc[nt][1] *= al0;
            oacc[nt][2] *= al1; oacc[nt][3] *= al1;
        }

        __syncthreads();   // all warps done with Ksm (S phase) before P overlay

        // ---- write P (tf32) into this warp's Ksm slice ----
        uint32_t* Psm = Ksm + wm * KST;
#pragma unroll
        for (int nt = 0; nt < 8; nt++) {
            *(uint2*)&Psm[grp * KST + nt * 8 + q * 2] =
                make_uint2(f2tf32(sacc[nt][0]), f2tf32(sacc[nt][1]));
            *(uint2*)&Psm[(grp + 8) * KST + nt * 8 + q * 2] =
                make_uint2(f2tf32(sacc[nt][2]), f2tf32(sacc[nt][3]));
        }
        __syncwarp();

        // ---- O += P V ----
#pragma unroll
        for (int ks = 0; ks < 8; ks++) {
            uint32_t af[4];
            af[0] = Psm[grp * KST + ks * 8 + q];
            af[1] = Psm[(grp + 8) * KST + ks * 8 + q];
            af[2] = Psm[grp * KST + ks * 8 + q + 4];
            af[3] = Psm[(grp + 8) * KST + ks * 8 + q + 4];
            uint32_t bf[8][2];
#pragma unroll
            for (int nt = 0; nt < 8; nt++) {
                bf[nt][0] = Vsm[(ks * 8 + q) * VST + nt * 8 + grp];
                bf[nt][1] = Vsm[(ks * 8 + q + 4) * VST + nt * 8 + grp];
            }
#pragma unroll
            for (int nt = 0; nt < 8; nt++)
                MMA_TF32(oacc[nt], af, bf[nt]);
        }
        __syncthreads();   // done with Ksm(P) & Vsm before next tile's loads
    }

    l0 += __shfl_xor_sync(0xffffffffu, l0, 1);
    l0 += __shfl_xor_sync(0xffffffffu, l0, 2);
    l1 += __shfl_xor_sync(0xffffffffu, l1, 1);
    l1 += __shfl_xor_sync(0xffffffffu, l1, 2);
    const float inv0 = 1.f / l0;
    const float inv1 = 1.f / l1;
#pragma unroll
    for (int nt = 0; nt < 8; nt++) {
        int col = nt * 8 + q * 2;
        *(float2*)(Og + base + (size_t)r0 * DD + col) =
            make_float2(oacc[nt][0] * inv0, oacc[nt][1] * inv0);
        *(float2*)(Og + base + (size_t)(r0 + 8) * DD + col) =
            make_float2(oacc[nt][2] * inv1, oacc[nt][3] * inv1);
    }
}

// ---------------------------------------------------------------------------
extern "C" void kernel_launch(void* const* d_in, const int* in_sizes, int n_in,
                              void* d_out, int out_size)
{
    (void)in_sizes; (void)n_in; (void)out_size;
    const float* x  = (const float*)d_in[0];
    const float* wq = (const float*)d_in[2];
    const float* bq = (const float*)d_in[3];
    const float* wk = (const float*)d_in[4];
    const float* bk = (const float*)d_in[5];
    const float* wv = (const float*)d_in[6];
    const float* bv = (const float*)d_in[7];
    const float* wo = (const float*)d_in[8];
    const float* bo = (const float*)d_in[9];
    float* out = (float*)d_out;

    float *We, *Qb, *Kb, *Vb, *Ob;
    cudaGetSymbolAddress((void**)&We, g_We);
    cudaGetSymbolAddress((void**)&Qb, g_Q);
    cudaGetSymbolAddress((void**)&Kb, g_K);
    cudaGetSymbolAddress((void**)&Vb, g_V);
    cudaGetSymbolAddress((void**)&Ob, g_O);

    expand_kernel<<<dim3(DD * DD / 256, 4), 256>>>(wq, wk, wv, wo);

    gemm_tf32<<<dim3(DD / 128, MM / 128, 3), 256>>>(
        x, We, We + DD * DD, We + 2 * DD * DD, bq, bk, bv, Qb, Kb, Vb);

    flash_mma<<<dim3(32, 16), 128>>>(Qb, Kb, Vb, Ob);

    gemm_tf32<<<dim3(DD / 128, MM / 128, 1), 256>>>(
        Ob, We + 3 * DD * DD, We + 3 * DD * DD, We + 3 * DD * DD,
        bo, bo, bo, out, out, out);
}